// round 14
// baseline (speedup 1.0000x reference)
#include <cuda_runtime.h>
#include <cuda_fp16.h>
#include <cstdint>

#define NHEADS 12
#define HD 64
#define BHT 96        // B * NHEADS
#define NSEQ 1024     // H*W
#define DIM 768
#define BROWS 8192    // B * NSEQ

// ---------------- scratch (device globals; no allocation) ----------------
__device__ __half g_xr[BROWS * DIM];        // fp16-rounded x
__device__ __half g_w1t[3 * DIM * DIM];     // fp16 qkv_w, transposed [n][k]
__device__ __half g_w2t[DIM * DIM];         // fp16 proj_w, transposed [n][k]
__device__ __half g_q[BHT * NSEQ * HD];     // fp16 [bh][n][d]
__device__ __half g_k[BHT * NSEQ * HD];     // fp16 [bh][n][d]
__device__ __half g_v[BHT * HD * NSEQ];     // fp16, TRANSPOSED [bh][d][n]
__device__ float  g_relh[BHT * 32 * 32 * 32];
__device__ float  g_relw[BHT * 32 * 32 * 32];
__device__ __half g_o[BROWS * DIM];         // fp16 attention output

// ---------------- helpers ---------------------------------------------------
__device__ __forceinline__ void mma_f16(float* d,
                                        unsigned a0, unsigned a1, unsigned a2, unsigned a3,
                                        unsigned b0, unsigned b1)
{
    asm volatile(
        "mma.sync.aligned.m16n8k16.row.col.f32.f16.f16.f32 "
        "{%0,%1,%2,%3}, {%4,%5,%6,%7}, {%8,%9}, {%0,%1,%2,%3};"
        : "+f"(d[0]), "+f"(d[1]), "+f"(d[2]), "+f"(d[3])
        : "r"(a0), "r"(a1), "r"(a2), "r"(a3), "r"(b0), "r"(b1));
}

__device__ __forceinline__ void cp16(uint32_t dst, const void* src) {
    asm volatile("cp.async.cg.shared.global [%0], [%1], 16;" :: "r"(dst), "l"(src));
}

#define LDSM4(r0, r1, r2, r3, addr) \
    asm volatile("ldmatrix.sync.aligned.m8n8.x4.shared.b16 {%0,%1,%2,%3}, [%4];" \
        : "=r"(r0), "=r"(r1), "=r"(r2), "=r"(r3) : "r"(addr))

// ---------------- pre-pass kernels ------------------------------------------
__global__ void __launch_bounds__(256) round_kernel(
    const float* __restrict__ src, __half* __restrict__ dst, int n8)
{
    int i = blockIdx.x * 256 + threadIdx.x;
    if (i < n8) {
        float4 v0 = ((const float4*)src)[2 * i];
        float4 v1 = ((const float4*)src)[2 * i + 1];
        __half2 h[4];
        h[0] = __floats2half2_rn(v0.x, v0.y);
        h[1] = __floats2half2_rn(v0.z, v0.w);
        h[2] = __floats2half2_rn(v1.x, v1.y);
        h[3] = __floats2half2_rn(v1.z, v1.w);
        ((uint4*)dst)[i] = *(uint4*)h;
    }
}

// dst[n][k] = fp16(src[k][n]).  src is K x N row-major fp32.
__global__ void __launch_bounds__(256) transpose_round_kernel(
    const float* __restrict__ src, __half* __restrict__ dst, int K, int N)
{
    __shared__ float tile[32][33];
    const int n0 = blockIdx.x * 32;
    const int k0 = blockIdx.y * 32;
    const int tx = threadIdx.x & 31;
    const int ty = threadIdx.x >> 5;   // 0..7
#pragma unroll
    for (int i = 0; i < 4; i++)
        tile[ty + i * 8][tx] = src[(k0 + ty + i * 8) * N + n0 + tx];
    __syncthreads();
#pragma unroll
    for (int i = 0; i < 4; i++)
        dst[(n0 + ty + i * 8) * K + k0 + tx] = __float2half_rn(tile[tx][ty + i * 8]);
}

// ---------------- fp16 GEMM: ldmatrix + 2-stage cp.async, BK=64 -------------
// BM=128, BN=128, BK=64(halves), 256 threads, warps 2(m) x 4(n), tile 64x32.
// smem rows: 144 B stride (72 halves), same conflict-free layout as attn.
#define MM_STG 18432                 // bytes per stage per matrix (128*144)
#define MM_SMEM_BYTES (4 * MM_STG)

template <int MODE>
__global__ void __launch_bounds__(256, 2) mm_kernel(
    const float* __restrict__ bias, float* __restrict__ C,
    int M, int N, int K)
{
    extern __shared__ char mmsm[];
    const __half* A  = (MODE == 0) ? g_o  : g_xr;
    const __half* Bt = (MODE == 0) ? g_w2t : g_w1t;

    const int bm = blockIdx.y * 128;
    const int bn = blockIdx.x * 128;
    const int t  = threadIdx.x;
    const int w  = t >> 5;
    const int lane = t & 31;
    const int g  = lane >> 2;
    const int tg = lane & 3;
    const int wm = w >> 2;
    const int wn = w & 3;

    const int ld_row = t >> 1;         // 0..127
    const int ld_h   = (t & 1) * 32;   // 0 or 32 (halves)

    const uint32_t sbase = (uint32_t)__cvta_generic_to_shared(mmsm);

    const uint32_t a_lm = (uint32_t)((wm * 64 + (lane & 15)) * 144 + (lane >> 4) * 16);
    const uint32_t b_lm = (uint32_t)((wn * 32 + (lane >> 4) * 8 + (lane & 7)) * 144
                                     + ((lane >> 3) & 1) * 16);

    float acc[4][4][4];
#pragma unroll
    for (int i = 0; i < 4; i++)
#pragma unroll
        for (int j = 0; j < 4; j++)
#pragma unroll
            for (int q = 0; q < 4; q++) acc[i][j][q] = 0.f;

    const int nk = K / 64;             // 12 for K=768

    auto issue = [&](int kt) {
        int st = kt & 1;
        const __half* ap = &A[(bm + ld_row) * K + kt * 64 + ld_h];
        uint32_t ad = sbase + st * MM_STG + ld_row * 144 + ld_h * 2;
        cp16(ad, ap);      cp16(ad + 16, ap + 8);
        cp16(ad + 32, ap + 16); cp16(ad + 48, ap + 24);
        const __half* bp = &Bt[(bn + ld_row) * K + kt * 64 + ld_h];
        uint32_t bd = sbase + 2 * MM_STG + st * MM_STG + ld_row * 144 + ld_h * 2;
        cp16(bd, bp);      cp16(bd + 16, bp + 8);
        cp16(bd + 32, bp + 16); cp16(bd + 48, bp + 24);
        asm volatile("cp.async.commit_group;");
    };

    issue(0);

    for (int kt = 0; kt < nk; kt++) {
        asm volatile("cp.async.wait_group 0;");
        __syncthreads();
        if (kt + 1 < nk) issue(kt + 1);

        const int st = kt & 1;
        const uint32_t abase = sbase + st * MM_STG + a_lm;
        const uint32_t bbase = sbase + 2 * MM_STG + st * MM_STG + b_lm;

#pragma unroll
        for (int ks = 0; ks < 4; ks++) {      // four k16 steps per 64-K slab
            unsigned af[4][4];
#pragma unroll
            for (int mt = 0; mt < 4; mt++)
                LDSM4(af[mt][0], af[mt][1], af[mt][2], af[mt][3],
                      abase + mt * 16 * 144 + ks * 32);
            unsigned bf[4][2];
#pragma unroll
            for (int np = 0; np < 2; np++)
                LDSM4(bf[2 * np][0], bf[2 * np][1], bf[2 * np + 1][0], bf[2 * np + 1][1],
                      bbase + np * 16 * 144 + ks * 32);
#pragma unroll
            for (int mt = 0; mt < 4; mt++)
#pragma unroll
                for (int nt = 0; nt < 4; nt++)
                    mma_f16(acc[mt][nt], af[mt][0], af[mt][1], af[mt][2], af[mt][3],
                            bf[nt][0], bf[nt][1]);
        }
    }

    // epilogue
#pragma unroll
    for (int mt = 0; mt < 4; mt++) {
#pragma unroll
        for (int nt = 0; nt < 4; nt++) {
            int row = bm + wm * 64 + mt * 16 + g;
            int col = bn + wn * 32 + nt * 8 + 2 * tg;
#pragma unroll
            for (int q = 0; q < 4; q++) {
                int r = row + (q >> 1) * 8;
                int c = col + (q & 1);
                float v = acc[mt][nt][q] + bias[c];
                if (MODE == 0) {
                    C[r * N + c] = v;
                } else {
                    const int b = r >> 10;
                    const int n = r & 1023;
                    const int which = c / 768;
                    const int rem = c - which * 768;
                    const int head = rem >> 6;
                    const int d = rem & 63;
                    __half rv = __float2half_rn(v);
                    if (which == 0)
                        g_q[((b * NHEADS + head) * NSEQ + n) * HD + d] = rv;
                    else if (which == 1)
                        g_k[((b * NHEADS + head) * NSEQ + n) * HD + d] = rv;
                    else   // V transposed: [bh][d][n]
                        g_v[((b * NHEADS + head) * HD + d) * NSEQ + n] = rv;
                }
            }
        }
    }
}

// ---------------- relative position bias: float4 smem dots ------------------
__global__ void __launch_bounds__(256) rel_kernel(
    const float* __restrict__ rph, const float* __restrict__ rpw)
{
    __shared__ float qrow[32 * 64];
    __shared__ float rh[32 * 68];
    __shared__ float rw[63 * 68];

    const int bh = blockIdx.x;
    const int qh = blockIdx.y;
    const int t  = threadIdx.x;

    for (int i = t; i < 32 * 64; i += 256) {
        int row = i >> 6, d = i & 63;
        qrow[i] = __half2float(g_q[((bh * NSEQ) + qh * 32 + row) * HD + d]);
        rh[row * 68 + d] = rph[(qh + row) * 64 + d];
    }
    for (int i = t; i < 63 * 64; i += 256) {
        int row = i >> 6, d = i & 63;
        rw[row * 68 + d] = rpw[i];
    }
    __syncthreads();

    for (int o = t; o < 2048; o += 256) {
        if (o < 1024) {
            int qw = o >> 5, kh = o & 31;
            const float4* a4 = (const float4*)&qrow[qw * 64];
            const float4* b4 = (const float4*)&rh[(31 - kh) * 68];
            float s = 0.f;
#pragma unroll
            for (int d = 0; d < 16; d++) {
                float4 av = a4[d], bv = b4[d];
                s += av.x * bv.x + av.y * bv.y + av.z * bv.z + av.w * bv.w;
            }
            g_relh[(((bh * 32 + qh) * 32 + qw) * 32) + kh] = s;
        } else {
            int oo = o - 1024;
            int qw = oo >> 5, kw = oo & 31;
            const float4* a4 = (const float4*)&qrow[qw * 64];
            const float4* b4 = (const float4*)&rw[(qw - kw + 31) * 68];
            float s = 0.f;
#pragma unroll
            for (int d = 0; d < 16; d++) {
                float4 av = a4[d], bv = b4[d];
                s += av.x * bv.x + av.y * bv.y + av.z * bv.z + av.w * bv.w;
            }
            g_relw[(((bh * 32 + qh) * 32 + qw) * 32) + kw] = s;
        }
    }
}

// ---------------- attention: QT=64, 256 threads, hoisted rel bias ----------
// smem BYTE offsets; half tiles use 72-half stride (144 B).
#define SMB_Q    0                          // [64][72] h = 9216
#define SMB_P    9216                       // [64][72] h = 9216
#define SMB_K    18432                      // 2 x [64][72] h = 18432
#define SMB_V    36864                      // 2 x [64][72] h = 18432
#define SMB_RH   55296                      // [64][32] f32 = 8192
#define SMB_RW   63488                      // 8192
#define SMB_SS   71680                      // [4][64] f32 = 1024
#define KVSTB    9216
#define ATTN_SMEM_BYTES 72704

__global__ void __launch_bounds__(256, 2) attn_kernel()
{
    extern __shared__ char smc[];
    __half* Qh   = (__half*)(smc + SMB_Q);
    __half* Pbuf = (__half*)(smc + SMB_P);
    float*  RH   = (float*)(smc + SMB_RH);
    float*  RW   = (float*)(smc + SMB_RW);
    float*  SS   = (float*)(smc + SMB_SS);

    const int qt = blockIdx.x;   // 0..15 (64 q rows each)
    const int bh = blockIdx.y;   // 0..95
    const int t  = threadIdx.x;
    const int w  = t >> 5;
    const int lane = t & 31;
    const int g  = lane >> 2;
    const int tg = lane & 3;
    const int wm = w >> 2;       // S-phase: 2(m) x 4(n)
    const int wn = w & 3;
    const int wr = w >> 1;       // PV-phase: 4(rows) x 2(d-halves)
    const int wd = w & 1;

    const uint32_t sbase = (uint32_t)__cvta_generic_to_shared(smc);

    // ldmatrix per-lane byte address components (stride 144 B)
    const uint32_t q_lm = (uint32_t)((wm * 32 + (lane & 15)) * 144 + (lane >> 4) * 16);
    const uint32_t k_lm = (uint32_t)((wn * 16 + (lane >> 4) * 8 + (lane & 7)) * 144
                                     + ((lane >> 3) & 1) * 16);
    const uint32_t p_lm = (uint32_t)((wr * 16 + (lane & 15)) * 144 + (lane >> 4) * 16);
    const uint32_t v_lm = (uint32_t)((wd * 32 + (lane >> 4) * 8 + (lane & 7)) * 144
                                     + ((lane >> 3) & 1) * 16);

    // load Q tile (64x64 halves), pre-scaled by 0.125 (exact in fp16)
    const __half2 hscale = __half2half2(__float2half_rn(0.125f));
#pragma unroll
    for (int f = 0; f < 2; f++) {
        int i = t + 256 * f;          // 512 x 8-half chunks
        int r = i >> 3;
        int c = (i & 7) * 8;
        uint4 u = *(const uint4*)&g_q[(bh * NSEQ + qt * 64 + r) * HD + c];
        __half2* hp = (__half2*)&u;
        hp[0] = __hmul2(hp[0], hscale);
        hp[1] = __hmul2(hp[1], hscale);
        hp[2] = __hmul2(hp[2], hscale);
        hp[3] = __hmul2(hp[3], hscale);
        *(uint4*)&Qh[r * 72 + c] = u;
    }
    // rel bias rows for 64 q rows
    for (int i = t; i < 64 * 32; i += 256) {
        int r = i >> 5, c = i & 31;
        int qn = qt * 64 + r;
        int qh = qn >> 5, qw = qn & 31;
        int base = ((bh * 32 + qh) * 32 + qw) * 32 + c;
        RH[i] = g_relh[base];
        RW[i] = g_relw[base];
    }

    // cp.async K/V tile kt (K: [key][d]; V: [d][key]; 64x64 halves each)
    auto issue = [&](int kt) {
        int st = kt & 1;
#pragma unroll
        for (int f = 0; f < 2; f++) {
            int fi = t + 256 * f;
            int row = fi >> 3;            // 0..63
            int ch  = (fi & 7) * 8;       // half offset
            cp16(sbase + SMB_K + st * KVSTB + row * 144 + ch * 2,
                 &g_k[(bh * NSEQ + kt * 64 + row) * HD + ch]);
            cp16(sbase + SMB_V + st * KVSTB + row * 144 + ch * 2,
                 &g_v[(bh * HD + row) * NSEQ + kt * 64 + ch]);
        }
        asm volatile("cp.async.commit_group;");
    };

    issue(0);
    __syncthreads();   // RW/RH (and Q) visible to all threads

    // hoist RW: kw independent of kt -> 16 tile-invariant values per thread
    float rwv[2][2][2][2];
#pragma unroll
    for (int mt = 0; mt < 2; mt++)
#pragma unroll
        for (int rh = 0; rh < 2; rh++) {
            int rr = wm * 32 + mt * 16 + g + rh * 8;
#pragma unroll
            for (int nt = 0; nt < 2; nt++)
#pragma unroll
                for (int qp = 0; qp < 2; qp++) {
                    int kw = (wn & 1) * 16 + nt * 8 + 2 * tg + qp;
                    rwv[mt][rh][nt][qp] = RW[rr * 32 + kw];
                }
        }

    float rsum[2][2] = {{0.f, 0.f}, {0.f, 0.f}};
    float po[4][4];
#pragma unroll
    for (int i = 0; i < 4; i++)
#pragma unroll
        for (int q = 0; q < 4; q++) po[i][q] = 0.f;

    for (int kt = 0; kt < 16; kt++) {
        const int st = kt & 1;
        asm volatile("cp.async.wait_group 0;");
        __syncthreads();             // K/V[st] ready; prior PV + P reads done
        if (kt + 1 < 16) issue(kt + 1);

        const uint32_t kb = sbase + SMB_K + st * KVSTB;
        const uint32_t vb = sbase + SMB_V + st * KVSTB;

        // RH: kh fixed per warp per tile
        const int kh = 2 * kt + (wn >> 1);
        float rhv[2][2];
#pragma unroll
        for (int mt = 0; mt < 2; mt++)
#pragma unroll
            for (int rh = 0; rh < 2; rh++) {
                int rr = wm * 32 + mt * 16 + g + rh * 8;
                rhv[mt][rh] = RH[rr * 32 + kh];
            }

        // ---- S = Q @ K^T (Q pre-scaled) ----
        float acc[2][2][4];
#pragma unroll
        for (int i = 0; i < 2; i++)
#pragma unroll
            for (int j = 0; j < 2; j++)
#pragma unroll
                for (int q = 0; q < 4; q++) acc[i][j][q] = 0.f;

#pragma unroll
        for (int ks = 0; ks < 4; ks++) {          // d: 4 x k16
            unsigned af[2][4];
#pragma unroll
            for (int mt = 0; mt < 2; mt++)
                LDSM4(af[mt][0], af[mt][1], af[mt][2], af[mt][3],
                      sbase + SMB_Q + q_lm + mt * 16 * 144 + ks * 32);
            unsigned bf[2][2];
            LDSM4(bf[0][0], bf[0][1], bf[1][0], bf[1][1], kb + k_lm + ks * 32);
#pragma unroll
            for (int mt = 0; mt < 2; mt++)
#pragma unroll
                for (int nt = 0; nt < 2; nt++)
                    mma_f16(acc[mt][nt], af[mt][0], af[mt][1], af[mt][2], af[mt][3],
                            bf[nt][0], bf[nt][1]);
        }

        // ---- P = exp(S + rh + rw) into Pbuf (half2); private row sums ------
#pragma unroll
        for (int mt = 0; mt < 2; mt++)
#pragma unroll
            for (int nt = 0; nt < 2; nt++) {
                int cl = wn * 16 + nt * 8 + 2 * tg;
#pragma unroll
                for (int rh = 0; rh < 2; rh++) {
                    int rr = wm * 32 + mt * 16 + g + rh * 8;
                    float e0 = __expf(acc[mt][nt][rh * 2]     + rhv[mt][rh] + rwv[mt][rh][nt][0]);
                    float e1 = __expf(acc[mt][nt][rh * 2 + 1] + rhv[mt][rh] + rwv[mt][rh][nt][1]);
                    rsum[mt][rh] += e0 + e1;
                    *(__half2*)&Pbuf[rr * 72 + cl] = __floats2half2_rn(e0, e1);
                }
            }
        __syncthreads();             // P ready

        // ---- PV: O += P @ V ----
#pragma unroll
        for (int ks = 0; ks < 4; ks++) {          // keys: 4 x k16
            unsigned a0, a1, a2, a3;
            LDSM4(a0, a1, a2, a3, sbase + SMB_P + p_lm + ks * 32);
            unsigned bf[4][2];
#pragma unroll
            for (int np = 0; np < 2; np++)
                LDSM4(bf[2 * np][0], bf[2 * np][1], bf[2 * np + 1][0], bf[2 * np + 1][1],
                      vb + v_lm + np * 16 * 144 + ks * 32);
#pragma unroll
            for (int nt = 0; nt < 4; nt++)
                mma_f16(po[nt], a0, a1, a2, a3, bf[nt][0], bf[nt][1]);
        }
    }

    // ---- row-sum reduction across wn warps ---------------------------------
    __syncthreads();
#pragma unroll
    for (int mt = 0; mt < 2; mt++)
#pragma unroll
        for (int rh = 0; rh < 2; rh++) {
            float v = rsum[mt][rh];
            v += __shfl_xor_sync(0xffffffffu, v, 1);
            v += __shfl_xor_sync(0xffffffffu, v, 2);
            if (tg == 0) SS[wn * 64 + wm * 32 + mt * 16 + g + rh * 8] = v;
        }
    __syncthreads();

    // ---- epilogue: normalize, write g_o (fp16) [b][n][head][d] --------------
    const int b = bh / NHEADS;
    const int head = bh % NHEADS;
    const int r0 = wr * 16 + g;
    const int r1 = r0 + 8;
    float s0 = SS[r0] + SS[64 + r0] + SS[128 + r0] + SS[192 + r0];
    float s1 = SS[r1] + SS[64 + r1] + SS[128 + r1] + SS[192 + r1];
    float i0 = 1.0f / s0;
    float i1 = 1.0f / s1;
#pragma unroll
    for (int nt = 0; nt < 4; nt++) {
        int dim = head * HD + wd * 32 + nt * 8 + 2 * tg;
        long o0 = (long)(b * NSEQ + qt * 64 + r0) * DIM + dim;
        long o1 = (long)(b * NSEQ + qt * 64 + r1) * DIM + dim;
        *(__half2*)&g_o[o0] = __floats2half2_rn(po[nt][0] * i0, po[nt][1] * i0);
        *(__half2*)&g_o[o1] = __floats2half2_rn(po[nt][2] * i1, po[nt][3] * i1);
    }
}

// ---------------- launch ---------------------------------------------------
extern "C" void kernel_launch(void* const* d_in, const int* in_sizes, int n_in,
                              void* d_out, int out_size)
{
    const float* x      = (const float*)d_in[0];
    const float* qkv_w  = (const float*)d_in[1];
    const float* qkv_b  = (const float*)d_in[2];
    const float* proj_w = (const float*)d_in[3];
    const float* proj_b = (const float*)d_in[4];
    const float* rph    = (const float*)d_in[5];
    const float* rpw    = (const float*)d_in[6];
    float* out = (float*)d_out;

    cudaFuncSetAttribute(attn_kernel,
                         cudaFuncAttributeMaxDynamicSharedMemorySize, ATTN_SMEM_BYTES);
    cudaFuncSetAttribute(mm_kernel<1>,
                         cudaFuncAttributeMaxDynamicSharedMemorySize, MM_SMEM_BYTES);
    cudaFuncSetAttribute(mm_kernel<0>,
                         cudaFuncAttributeMaxDynamicSharedMemorySize, MM_SMEM_BYTES);

    __half* xr = nullptr; __half* w1t = nullptr; __half* w2t = nullptr;
    cudaGetSymbolAddress((void**)&xr,  g_xr);
    cudaGetSymbolAddress((void**)&w1t, g_w1t);
    cudaGetSymbolAddress((void**)&w2t, g_w2t);

    // 0) pre-round x; pre-round + transpose weights (fp16)
    {
        int n8x = BROWS * DIM / 8;
        round_kernel<<<(n8x + 255) / 256, 256>>>(x, xr, n8x);
        transpose_round_kernel<<<dim3(3 * DIM / 32, DIM / 32), 256>>>(
            qkv_w, w1t, DIM, 3 * DIM);
        transpose_round_kernel<<<dim3(DIM / 32, DIM / 32), 256>>>(
            proj_w, w2t, DIM, DIM);
    }

    // 1) QKV projection: (8192,768) @ (768,2304) -> q/k (row) + v (transposed)
    mm_kernel<1><<<dim3(2304 / 128, 8192 / 128), 256, MM_SMEM_BYTES>>>(
        qkv_b, nullptr, BROWS, 3 * DIM, DIM);

    // 2) decomposed relative position bias
    rel_kernel<<<dim3(BHT, 32), 256>>>(rph, rpw);

    // 3) attention: 64q x 64k tiles, 256 threads, hoisted rel bias
    attn_kernel<<<dim3(NSEQ / 64, BHT), 256, ATTN_SMEM_BYTES>>>();

    // 4) output projection: (8192,768) @ (768,768) + bias -> d_out (fp32)
    mm_kernel<0><<<dim3(DIM / 128, 8192 / 128), 256, MM_SMEM_BYTES>>>(
        proj_b, out, BROWS, DIM, DIM);
}

// round 15
// speedup vs baseline: 1.0720x; 1.0720x over previous
#include <cuda_runtime.h>
#include <cuda_fp16.h>
#include <cstdint>

#define NHEADS 12
#define HD 64
#define BHT 96        // B * NHEADS
#define NSEQ 1024     // H*W
#define DIM 768
#define BROWS 8192    // B * NSEQ

// ---------------- scratch (device globals; no allocation) ----------------
__device__ __half g_xr[BROWS * DIM];        // fp16-rounded x
__device__ __half g_w1t[3 * DIM * DIM];     // fp16 qkv_w, transposed [n][k]
__device__ __half g_w2t[DIM * DIM];         // fp16 proj_w, transposed [n][k]
__device__ __half g_q[BHT * NSEQ * HD];     // fp16 [bh][n][d]
__device__ __half g_k[BHT * NSEQ * HD];     // fp16 [bh][n][d]
__device__ __half g_v[BHT * HD * NSEQ];     // fp16, TRANSPOSED [bh][d][n]
__device__ float  g_relh[BHT * 32 * 32 * 32];
__device__ float  g_relw[BHT * 32 * 32 * 32];
__device__ __half g_o[BROWS * DIM];         // fp16 attention output

// ---------------- helpers ---------------------------------------------------
__device__ __forceinline__ void mma_f16(float* d,
                                        unsigned a0, unsigned a1, unsigned a2, unsigned a3,
                                        unsigned b0, unsigned b1)
{
    asm volatile(
        "mma.sync.aligned.m16n8k16.row.col.f32.f16.f16.f32 "
        "{%0,%1,%2,%3}, {%4,%5,%6,%7}, {%8,%9}, {%0,%1,%2,%3};"
        : "+f"(d[0]), "+f"(d[1]), "+f"(d[2]), "+f"(d[3])
        : "r"(a0), "r"(a1), "r"(a2), "r"(a3), "r"(b0), "r"(b1));
}

__device__ __forceinline__ void cp16(uint32_t dst, const void* src) {
    asm volatile("cp.async.cg.shared.global [%0], [%1], 16;" :: "r"(dst), "l"(src));
}

#define LDSM4(r0, r1, r2, r3, addr) \
    asm volatile("ldmatrix.sync.aligned.m8n8.x4.shared.b16 {%0,%1,%2,%3}, [%4];" \
        : "=r"(r0), "=r"(r1), "=r"(r2), "=r"(r3) : "r"(addr))

// ---------------- pre-pass kernels ------------------------------------------
__global__ void __launch_bounds__(256) round_kernel(
    const float* __restrict__ src, __half* __restrict__ dst, int n8)
{
    int i = blockIdx.x * 256 + threadIdx.x;
    if (i < n8) {
        float4 v0 = ((const float4*)src)[2 * i];
        float4 v1 = ((const float4*)src)[2 * i + 1];
        __half2 h[4];
        h[0] = __floats2half2_rn(v0.x, v0.y);
        h[1] = __floats2half2_rn(v0.z, v0.w);
        h[2] = __floats2half2_rn(v1.x, v1.y);
        h[3] = __floats2half2_rn(v1.z, v1.w);
        ((uint4*)dst)[i] = *(uint4*)h;
    }
}

// dst[n][k] = fp16(src[k][n]).  src is K x N row-major fp32.
__global__ void __launch_bounds__(256) transpose_round_kernel(
    const float* __restrict__ src, __half* __restrict__ dst, int K, int N)
{
    __shared__ float tile[32][33];
    const int n0 = blockIdx.x * 32;
    const int k0 = blockIdx.y * 32;
    const int tx = threadIdx.x & 31;
    const int ty = threadIdx.x >> 5;   // 0..7
#pragma unroll
    for (int i = 0; i < 4; i++)
        tile[ty + i * 8][tx] = src[(k0 + ty + i * 8) * N + n0 + tx];
    __syncthreads();
#pragma unroll
    for (int i = 0; i < 4; i++)
        dst[(n0 + ty + i * 8) * K + k0 + tx] = __float2half_rn(tile[tx][ty + i * 8]);
}

// ---------------- fp16 GEMM: ldmatrix + 2-stage cp.async, BK=32 -------------
// BM=128, BN=128, BK=32(halves), 256 threads, warps 2(m) x 4(n), tile 64x32.
#define MM_STG 10240                 // bytes per stage per matrix (128*80)
#define MM_SMEM_BYTES (4 * MM_STG)

template <int MODE>
__global__ void __launch_bounds__(256, 2) mm_kernel(
    const float* __restrict__ bias, float* __restrict__ C,
    int M, int N, int K)
{
    extern __shared__ char mmsm[];
    const __half* A  = (MODE == 0) ? g_o  : g_xr;
    const __half* Bt = (MODE == 0) ? g_w2t : g_w1t;

    const int bm = blockIdx.y * 128;
    const int bn = blockIdx.x * 128;
    const int t  = threadIdx.x;
    const int w  = t >> 5;
    const int lane = t & 31;
    const int g  = lane >> 2;
    const int tg = lane & 3;
    const int wm = w >> 2;
    const int wn = w & 3;

    const int ld_row = t >> 1;         // 0..127
    const int ld_h   = (t & 1) * 16;   // 0 or 16 (halves)

    const uint32_t sbase = (uint32_t)__cvta_generic_to_shared(mmsm);

    const uint32_t a_lm = (uint32_t)((wm * 64 + (lane & 15)) * 80 + (lane >> 4) * 16);
    const uint32_t b_lm = (uint32_t)((wn * 32 + (lane >> 4) * 8 + (lane & 7)) * 80
                                     + ((lane >> 3) & 1) * 16);

    float acc[4][4][4];
#pragma unroll
    for (int i = 0; i < 4; i++)
#pragma unroll
        for (int j = 0; j < 4; j++)
#pragma unroll
            for (int q = 0; q < 4; q++) acc[i][j][q] = 0.f;

    const int nk = K / 32;

    auto issue = [&](int kt) {
        int st = kt & 1;
        const __half* ap = &A[(bm + ld_row) * K + kt * 32 + ld_h];
        uint32_t ad = sbase + st * MM_STG + ld_row * 80 + ld_h * 2;
        cp16(ad, ap); cp16(ad + 16, ap + 8);
        const __half* bp = &Bt[(bn + ld_row) * K + kt * 32 + ld_h];
        uint32_t bd = sbase + 2 * MM_STG + st * MM_STG + ld_row * 80 + ld_h * 2;
        cp16(bd, bp); cp16(bd + 16, bp + 8);
        asm volatile("cp.async.commit_group;");
    };

    issue(0);

    for (int kt = 0; kt < nk; kt++) {
        asm volatile("cp.async.wait_group 0;");
        __syncthreads();
        if (kt + 1 < nk) issue(kt + 1);

        const int st = kt & 1;
        const uint32_t abase = sbase + st * MM_STG + a_lm;
        const uint32_t bbase = sbase + 2 * MM_STG + st * MM_STG + b_lm;

#pragma unroll
        for (int ks = 0; ks < 2; ks++) {
            unsigned af[4][4];
#pragma unroll
            for (int mt = 0; mt < 4; mt++)
                LDSM4(af[mt][0], af[mt][1], af[mt][2], af[mt][3],
                      abase + mt * 16 * 80 + ks * 32);
            unsigned bf[4][2];
#pragma unroll
            for (int np = 0; np < 2; np++)
                LDSM4(bf[2 * np][0], bf[2 * np][1], bf[2 * np + 1][0], bf[2 * np + 1][1],
                      bbase + np * 16 * 80 + ks * 32);
#pragma unroll
            for (int mt = 0; mt < 4; mt++)
#pragma unroll
                for (int nt = 0; nt < 4; nt++)
                    mma_f16(acc[mt][nt], af[mt][0], af[mt][1], af[mt][2], af[mt][3],
                            bf[nt][0], bf[nt][1]);
        }
    }

    // epilogue
#pragma unroll
    for (int mt = 0; mt < 4; mt++) {
#pragma unroll
        for (int nt = 0; nt < 4; nt++) {
            int row = bm + wm * 64 + mt * 16 + g;
            int col = bn + wn * 32 + nt * 8 + 2 * tg;
#pragma unroll
            for (int q = 0; q < 4; q++) {
                int r = row + (q >> 1) * 8;
                int c = col + (q & 1);
                float v = acc[mt][nt][q] + bias[c];
                if (MODE == 0) {
                    C[r * N + c] = v;
                } else {
                    const int b = r >> 10;
                    const int n = r & 1023;
                    const int which = c / 768;
                    const int rem = c - which * 768;
                    const int head = rem >> 6;
                    const int d = rem & 63;
                    __half rv = __float2half_rn(v);
                    if (which == 0)
                        g_q[((b * NHEADS + head) * NSEQ + n) * HD + d] = rv;
                    else if (which == 1)
                        g_k[((b * NHEADS + head) * NSEQ + n) * HD + d] = rv;
                    else   // V transposed: [bh][d][n]
                        g_v[((b * NHEADS + head) * HD + d) * NSEQ + n] = rv;
                }
            }
        }
    }
}

// ---------------- relative position bias: float4 smem dots ------------------
__global__ void __launch_bounds__(256) rel_kernel(
    const float* __restrict__ rph, const float* __restrict__ rpw)
{
    __shared__ float qrow[32 * 64];
    __shared__ float rh[32 * 68];
    __shared__ float rw[63 * 68];

    const int bh = blockIdx.x;
    const int qh = blockIdx.y;
    const int t  = threadIdx.x;

    for (int i = t; i < 32 * 64; i += 256) {
        int row = i >> 6, d = i & 63;
        qrow[i] = __half2float(g_q[((bh * NSEQ) + qh * 32 + row) * HD + d]);
        rh[row * 68 + d] = rph[(qh + row) * 64 + d];
    }
    for (int i = t; i < 63 * 64; i += 256) {
        int row = i >> 6, d = i & 63;
        rw[row * 68 + d] = rpw[i];
    }
    __syncthreads();

    for (int o = t; o < 2048; o += 256) {
        if (o < 1024) {
            int qw = o >> 5, kh = o & 31;
            const float4* a4 = (const float4*)&qrow[qw * 64];
            const float4* b4 = (const float4*)&rh[(31 - kh) * 68];
            float s = 0.f;
#pragma unroll
            for (int d = 0; d < 16; d++) {
                float4 av = a4[d], bv = b4[d];
                s += av.x * bv.x + av.y * bv.y + av.z * bv.z + av.w * bv.w;
            }
            g_relh[(((bh * 32 + qh) * 32 + qw) * 32) + kh] = s;
        } else {
            int oo = o - 1024;
            int qw = oo >> 5, kw = oo & 31;
            const float4* a4 = (const float4*)&qrow[qw * 64];
            const float4* b4 = (const float4*)&rw[(qw - kw + 31) * 68];
            float s = 0.f;
#pragma unroll
            for (int d = 0; d < 16; d++) {
                float4 av = a4[d], bv = b4[d];
                s += av.x * bv.x + av.y * bv.y + av.z * bv.z + av.w * bv.w;
            }
            g_relw[(((bh * 32 + qh) * 32 + qw) * 32) + kw] = s;
        }
    }
}

// ---------------- attention: QT=64, 256 threads, Q frags in registers -------
// smem BYTE offsets; half tiles use 72-half stride (144 B).
#define SMB_Q    0                          // [64][72] h = 9216
#define SMB_P    9216                       // [64][72] h = 9216
#define SMB_K    18432                      // 2 x [64][72] h = 18432
#define SMB_V    36864                      // 2 x [64][72] h = 18432
#define SMB_RH   55296                      // [64][32] f32 = 8192
#define SMB_RW   63488                      // 8192
#define SMB_SS   71680                      // [4][64] f32 = 1024
#define KVSTB    9216
#define ATTN_SMEM_BYTES 72704

__global__ void __launch_bounds__(256, 2) attn_kernel()
{
    extern __shared__ char smc[];
    __half* Qh   = (__half*)(smc + SMB_Q);
    __half* Pbuf = (__half*)(smc + SMB_P);
    float*  RH   = (float*)(smc + SMB_RH);
    float*  RW   = (float*)(smc + SMB_RW);
    float*  SS   = (float*)(smc + SMB_SS);

    const int qt = blockIdx.x;   // 0..15 (64 q rows each)
    const int bh = blockIdx.y;   // 0..95
    const int t  = threadIdx.x;
    const int w  = t >> 5;
    const int lane = t & 31;
    const int g  = lane >> 2;
    const int tg = lane & 3;
    const int wm = w >> 2;       // S-phase: 2(m) x 4(n)
    const int wn = w & 3;
    const int wr = w >> 1;       // PV-phase: 4(rows) x 2(d-halves)
    const int wd = w & 1;

    const uint32_t sbase = (uint32_t)__cvta_generic_to_shared(smc);

    // ldmatrix per-lane byte address components (stride 144 B)
    const uint32_t q_lm = (uint32_t)((wm * 32 + (lane & 15)) * 144 + (lane >> 4) * 16);
    const uint32_t k_lm = (uint32_t)((wn * 16 + (lane >> 4) * 8 + (lane & 7)) * 144
                                     + ((lane >> 3) & 1) * 16);
    const uint32_t p_lm = (uint32_t)((wr * 16 + (lane & 15)) * 144 + (lane >> 4) * 16);
    const uint32_t v_lm = (uint32_t)((wd * 32 + (lane >> 4) * 8 + (lane & 7)) * 144
                                     + ((lane >> 3) & 1) * 16);

    // load Q tile (64x64 halves), pre-scaled by 0.125 (exact in fp16)
    const __half2 hscale = __half2half2(__float2half_rn(0.125f));
#pragma unroll
    for (int f = 0; f < 2; f++) {
        int i = t + 256 * f;          // 512 x 8-half chunks
        int r = i >> 3;
        int c = (i & 7) * 8;
        uint4 u = *(const uint4*)&g_q[(bh * NSEQ + qt * 64 + r) * HD + c];
        __half2* hp = (__half2*)&u;
        hp[0] = __hmul2(hp[0], hscale);
        hp[1] = __hmul2(hp[1], hscale);
        hp[2] = __hmul2(hp[2], hscale);
        hp[3] = __hmul2(hp[3], hscale);
        *(uint4*)&Qh[r * 72 + c] = u;
    }
    // rel bias rows for 64 q rows
    for (int i = t; i < 64 * 32; i += 256) {
        int r = i >> 5, c = i & 31;
        int qn = qt * 64 + r;
        int qh = qn >> 5, qw = qn & 31;
        int base = ((bh * 32 + qh) * 32 + qw) * 32 + c;
        RH[i] = g_relh[base];
        RW[i] = g_relw[base];
    }

    // cp.async K/V tile kt (K: [key][d]; V: [d][key]; 64x64 halves each)
    auto issue = [&](int kt) {
        int st = kt & 1;
#pragma unroll
        for (int f = 0; f < 2; f++) {
            int fi = t + 256 * f;
            int row = fi >> 3;            // 0..63
            int ch  = (fi & 7) * 8;       // half offset
            cp16(sbase + SMB_K + st * KVSTB + row * 144 + ch * 2,
                 &g_k[(bh * NSEQ + kt * 64 + row) * HD + ch]);
            cp16(sbase + SMB_V + st * KVSTB + row * 144 + ch * 2,
                 &g_v[(bh * HD + row) * NSEQ + kt * 64 + ch]);
        }
        asm volatile("cp.async.commit_group;");
    };

    issue(0);
    __syncthreads();   // Q/RW/RH visible to all threads

    // hoist Q fragments into registers (tile-invariant across all 16 K-tiles)
    unsigned qf[2][4][4];
#pragma unroll
    for (int mt = 0; mt < 2; mt++)
#pragma unroll
        for (int ks = 0; ks < 4; ks++)
            LDSM4(qf[mt][ks][0], qf[mt][ks][1], qf[mt][ks][2], qf[mt][ks][3],
                  sbase + SMB_Q + q_lm + mt * 16 * 144 + ks * 32);

    // hoist RW: kw independent of kt -> 16 tile-invariant values per thread
    float rwv[2][2][2][2];
#pragma unroll
    for (int mt = 0; mt < 2; mt++)
#pragma unroll
        for (int rh = 0; rh < 2; rh++) {
            int rr = wm * 32 + mt * 16 + g + rh * 8;
#pragma unroll
            for (int nt = 0; nt < 2; nt++)
#pragma unroll
                for (int qp = 0; qp < 2; qp++) {
                    int kw = (wn & 1) * 16 + nt * 8 + 2 * tg + qp;
                    rwv[mt][rh][nt][qp] = RW[rr * 32 + kw];
                }
        }

    float rsum[2][2] = {{0.f, 0.f}, {0.f, 0.f}};
    float po[4][4];
#pragma unroll
    for (int i = 0; i < 4; i++)
#pragma unroll
        for (int q = 0; q < 4; q++) po[i][q] = 0.f;

    for (int kt = 0; kt < 16; kt++) {
        const int st = kt & 1;
        asm volatile("cp.async.wait_group 0;");
        __syncthreads();             // K/V[st] ready; prior PV + P reads done
        if (kt + 1 < 16) issue(kt + 1);

        const uint32_t kb = sbase + SMB_K + st * KVSTB;
        const uint32_t vb = sbase + SMB_V + st * KVSTB;

        // RH: kh fixed per warp per tile
        const int kh = 2 * kt + (wn >> 1);
        float rhv[2][2];
#pragma unroll
        for (int mt = 0; mt < 2; mt++)
#pragma unroll
            for (int rh = 0; rh < 2; rh++) {
                int rr = wm * 32 + mt * 16 + g + rh * 8;
                rhv[mt][rh] = RH[rr * 32 + kh];
            }

        // ---- S = Q @ K^T (Q pre-scaled, fragments in registers) ----
        float acc[2][2][4];
#pragma unroll
        for (int i = 0; i < 2; i++)
#pragma unroll
            for (int j = 0; j < 2; j++)
#pragma unroll
                for (int q = 0; q < 4; q++) acc[i][j][q] = 0.f;

#pragma unroll
        for (int ks = 0; ks < 4; ks++) {          // d: 4 x k16
            unsigned bf[2][2];
            LDSM4(bf[0][0], bf[0][1], bf[1][0], bf[1][1], kb + k_lm + ks * 32);
#pragma unroll
            for (int mt = 0; mt < 2; mt++)
#pragma unroll
                for (int nt = 0; nt < 2; nt++)
                    mma_f16(acc[mt][nt], qf[mt][ks][0], qf[mt][ks][1],
                            qf[mt][ks][2], qf[mt][ks][3], bf[nt][0], bf[nt][1]);
        }

        // ---- P = exp(S + rh + rw) into Pbuf (half2); private row sums ------
#pragma unroll
        for (int mt = 0; mt < 2; mt++)
#pragma unroll
            for (int nt = 0; nt < 2; nt++) {
                int cl = wn * 16 + nt * 8 + 2 * tg;
#pragma unroll
                for (int rh = 0; rh < 2; rh++) {
                    int rr = wm * 32 + mt * 16 + g + rh * 8;
                    float e0 = __expf(acc[mt][nt][rh * 2]     + rhv[mt][rh] + rwv[mt][rh][nt][0]);
                    float e1 = __expf(acc[mt][nt][rh * 2 + 1] + rhv[mt][rh] + rwv[mt][rh][nt][1]);
                    rsum[mt][rh] += e0 + e1;
                    *(__half2*)&Pbuf[rr * 72 + cl] = __floats2half2_rn(e0, e1);
                }
            }
        __syncthreads();             // P ready

        // ---- PV: O += P @ V ----
#pragma unroll
        for (int ks = 0; ks < 4; ks++) {          // keys: 4 x k16
            unsigned a0, a1, a2, a3;
            LDSM4(a0, a1, a2, a3, sbase + SMB_P + p_lm + ks * 32);
            unsigned bf[4][2];
#pragma unroll
            for (int np = 0; np < 2; np++)
                LDSM4(bf[2 * np][0], bf[2 * np][1], bf[2 * np + 1][0], bf[2 * np + 1][1],
                      vb + v_lm + np * 16 * 144 + ks * 32);
#pragma unroll
            for (int nt = 0; nt < 4; nt++)
                mma_f16(po[nt], a0, a1, a2, a3, bf[nt][0], bf[nt][1]);
        }
    }

    // ---- row-sum reduction across wn warps ---------------------------------
    __syncthreads();
#pragma unroll
    for (int mt = 0; mt < 2; mt++)
#pragma unroll
        for (int rh = 0; rh < 2; rh++) {
            float v = rsum[mt][rh];
            v += __shfl_xor_sync(0xffffffffu, v, 1);
            v += __shfl_xor_sync(0xffffffffu, v, 2);
            if (tg == 0) SS[wn * 64 + wm * 32 + mt * 16 + g + rh * 8] = v;
        }
    __syncthreads();

    // ---- epilogue: normalize, write g_o (fp16) [b][n][head][d] --------------
    const int b = bh / NHEADS;
    const int head = bh % NHEADS;
    const int r0 = wr * 16 + g;
    const int r1 = r0 + 8;
    float s0 = SS[r0] + SS[64 + r0] + SS[128 + r0] + SS[192 + r0];
    float s1 = SS[r1] + SS[64 + r1] + SS[128 + r1] + SS[192 + r1];
    float i0 = 1.0f / s0;
    float i1 = 1.0f / s1;
#pragma unroll
    for (int nt = 0; nt < 4; nt++) {
        int dim = head * HD + wd * 32 + nt * 8 + 2 * tg;
        long o0 = (long)(b * NSEQ + qt * 64 + r0) * DIM + dim;
        long o1 = (long)(b * NSEQ + qt * 64 + r1) * DIM + dim;
        *(__half2*)&g_o[o0] = __floats2half2_rn(po[nt][0] * i0, po[nt][1] * i0);
        *(__half2*)&g_o[o1] = __floats2half2_rn(po[nt][2] * i1, po[nt][3] * i1);
    }
}

// ---------------- launch ---------------------------------------------------
extern "C" void kernel_launch(void* const* d_in, const int* in_sizes, int n_in,
                              void* d_out, int out_size)
{
    const float* x      = (const float*)d_in[0];
    const float* qkv_w  = (const float*)d_in[1];
    const float* qkv_b  = (const float*)d_in[2];
    const float* proj_w = (const float*)d_in[3];
    const float* proj_b = (const float*)d_in[4];
    const float* rph    = (const float*)d_in[5];
    const float* rpw    = (const float*)d_in[6];
    float* out = (float*)d_out;

    cudaFuncSetAttribute(attn_kernel,
                         cudaFuncAttributeMaxDynamicSharedMemorySize, ATTN_SMEM_BYTES);
    cudaFuncSetAttribute(mm_kernel<1>,
                         cudaFuncAttributeMaxDynamicSharedMemorySize, MM_SMEM_BYTES);
    cudaFuncSetAttribute(mm_kernel<0>,
                         cudaFuncAttributeMaxDynamicSharedMemorySize, MM_SMEM_BYTES);

    __half* xr = nullptr; __half* w1t = nullptr; __half* w2t = nullptr;
    cudaGetSymbolAddress((void**)&xr,  g_xr);
    cudaGetSymbolAddress((void**)&w1t, g_w1t);
    cudaGetSymbolAddress((void**)&w2t, g_w2t);

    // 0) pre-round x; pre-round + transpose weights (fp16)
    {
        int n8x = BROWS * DIM / 8;
        round_kernel<<<(n8x + 255) / 256, 256>>>(x, xr, n8x);
        transpose_round_kernel<<<dim3(3 * DIM / 32, DIM / 32), 256>>>(
            qkv_w, w1t, DIM, 3 * DIM);
        transpose_round_kernel<<<dim3(DIM / 32, DIM / 32), 256>>>(
            proj_w, w2t, DIM, DIM);
    }

    // 1) QKV projection: (8192,768) @ (768,2304) -> q/k (row) + v (transposed)
    mm_kernel<1><<<dim3(2304 / 128, 8192 / 128), 256, MM_SMEM_BYTES>>>(
        qkv_b, nullptr, BROWS, 3 * DIM, DIM);

    // 2) decomposed relative position bias
    rel_kernel<<<dim3(BHT, 32), 256>>>(rph, rpw);

    // 3) attention: 64q x 64k tiles, 256 threads, Q frags in registers
    attn_kernel<<<dim3(NSEQ / 64, BHT), 256, ATTN_SMEM_BYTES>>>();

    // 4) output projection: (8192,768) @ (768,768) + bias -> d_out (fp32)
    mm_kernel<0><<<dim3(DIM / 128, 8192 / 128), 256, MM_SMEM_BYTES>>>(
        proj_b, out, BROWS, DIM, DIM);
}